// round 13
// baseline (speedup 1.0000x reference)
#include <cuda_runtime.h>
#include <cuda_fp16.h>
#include <cstdint>

// LightGCN propagation, pull formulation, fp16 storage / fp32 accumulate.
// Build: [convert (stream 2) || hist -> fused single-pass scan -> fill] -> pulls.
// Dtype of edge_index (int32 vs int64, JAX x64 silently downcasts) is decided
// per-block inside hist/fill. Scan uses decoupled lookback (147 blocks, all
// co-resident on 148 SMs). Scratch (g_deg, scan states, ticket) is re-zeroed
// by its consumers so every graph replay sees a clean state.
//   h1 = fp16(A h0) ; h2 = fp16(A h1)
//   out = 0.25 * (x0_fp32 + h1 + h2 + A h2)

#define N_USERS   100000
#define N_ITEMS   50000
#define N_TOTAL   150000
#define EMB_DIM   64
#define N_EDGES   2000000
#define N_ELEMS   (N_TOTAL * EMB_DIM)
#define N_F4      (N_ELEMS / 4)            // 2,400,000 uint2 units

#define SCAN_BLK  1024
#define N_SCANBLK ((N_TOTAL + SCAN_BLK - 1) / SCAN_BLK)   // 147

// fp16 feature buffers: 64 halves = 16 uint2 per row (19.2 MB each)
__device__ uint2 g_h0[N_F4];
__device__ uint2 g_h1[N_F4];
__device__ uint2 g_h2[N_F4];

// CSR scratch (zero at module load; re-zeroed after each use)
__device__ int                g_deg[N_TOTAL];
__device__ int                g_off[N_TOTAL + 1];  // post-fill: g_off[r] = start(r+1)
__device__ unsigned long long g_scanstate[N_SCANBLK];  // (flag<<32)|value
__device__ int                g_scan_ticket;
__device__ int2               g_cw[N_EDGES];       // {col, weight-bits}, row-sorted

// ---------------------------------------------------------------------------
__device__ __forceinline__ uint2 pack_h4(float4 v) {
    __half2 a = __float22half2_rn(make_float2(v.x, v.y));
    __half2 b = __float22half2_rn(make_float2(v.z, v.w));
    uint2 r;
    r.x = *(unsigned int*)&a;
    r.y = *(unsigned int*)&b;
    return r;
}

// ---------------------------------------------------------------------------
// per-block dtype check: warp 0 reads 32 leading entries as int64; real int64
// data is always in [0, N_TOTAL); int32 data read as int64 fuses two random
// indices and fails the range test with probability 1 (32 samples).
// Call at block start (contains __syncthreads).
// ---------------------------------------------------------------------------
__device__ __forceinline__ int block_idx_is64(const void* edge_index) {
    __shared__ int flag;
    if (threadIdx.x < 32) {
        long long v = ((const long long*)edge_index)[threadIdx.x];
        int bad = (v < 0 || v >= N_TOTAL);
        unsigned m = __ballot_sync(0xffffffffu, bad);
        if (threadIdx.x == 0) flag = (m == 0);
    }
    __syncthreads();
    return flag;
}

// ---------------------------------------------------------------------------
// convert x0 -> fp16 h0 (stream 2, concurrent with the CSR build)
// ---------------------------------------------------------------------------
__global__ void convert_kernel(const float4* __restrict__ user,
                               const float4* __restrict__ item) {
    int i = blockIdx.x * blockDim.x + threadIdx.x;
    if (i >= N_F4) return;
    const int USER_F4 = (N_USERS * EMB_DIM) / 4;
    float4 v = (i < USER_F4) ? __ldg(&user[i]) : __ldg(&item[i - USER_F4]);
    g_h0[i] = pack_h4(v);
}

// ---------------------------------------------------------------------------
__global__ void hist_kernel(const void* __restrict__ edge_index) {
    int is64 = block_idx_is64(edge_index);
    int e = blockIdx.x * blockDim.x + threadIdx.x;
    if (e >= N_EDGES) return;
    int r;
    if (is64) r = (int)__ldg(&((const long long*)edge_index)[e]);
    else      r = __ldg(&((const int*)edge_index)[e]);
    atomicAdd(&g_deg[r], 1);
}

// ---------------------------------------------------------------------------
// fused scan: block-local shfl scan + decoupled warp-parallel lookback.
// Writes g_off[i+1] = global inclusive prefix of g_deg, g_off[0] = 0,
// zeroes g_deg for the next call. Last-finishing block resets scan states.
// ---------------------------------------------------------------------------
__global__ void scan_kernel() {
    __shared__ int warpsum[32];
    __shared__ int sh_excl;
    int b = blockIdx.x;
    int i = b * SCAN_BLK + threadIdx.x;
    int lane = threadIdx.x & 31;
    int wid  = threadIdx.x >> 5;
    int v = (i < N_TOTAL) ? g_deg[i] : 0;

    int x = v;
#pragma unroll
    for (int d = 1; d < 32; d <<= 1) {
        int y = __shfl_up_sync(0xffffffffu, x, d);
        if (lane >= d) x += y;
    }
    if (lane == 31) warpsum[wid] = x;
    __syncthreads();
    if (wid == 0) {
        int s = warpsum[lane];
#pragma unroll
        for (int d = 1; d < 32; d <<= 1) {
            int y = __shfl_up_sync(0xffffffffu, s, d);
            if (lane >= d) s += y;
        }
        warpsum[lane] = s;
    }
    __syncthreads();
    int incl  = x + ((wid > 0) ? warpsum[wid - 1] : 0);
    int total = warpsum[31];

    // publish + lookback (warp 0)
    if (wid == 0) {
        if (b == 0) {
            if (lane == 0) {
                atomicExch(&g_scanstate[0], (2ULL << 32) | (unsigned)total);
                sh_excl = 0;
            }
        } else {
            if (lane == 0)
                atomicExch(&g_scanstate[b], (1ULL << 32) | (unsigned)total);
            __syncwarp();
            long long excl = 0;
            int base = b - 1;
            while (true) {
                int idx = base - lane;                 // lane 0 = closest
                bool active = (idx >= 0);
                unsigned long long st =
                    active ? atomicAdd(&g_scanstate[idx], 0ULL) : 0ULL;
                while (__ballot_sync(0xffffffffu,
                                     active && (unsigned)(st >> 32) == 0)) {
                    if (active && (unsigned)(st >> 32) == 0)
                        st = atomicAdd(&g_scanstate[idx], 0ULL);
                }
                unsigned flag = active ? (unsigned)(st >> 32) : 1u;
                unsigned val  = active ? (unsigned)st : 0u;
                unsigned pmask = __ballot_sync(0xffffffffu, flag == 2);
                if (pmask) {
                    int firstp = __ffs(pmask) - 1;     // closest prefix lane
                    unsigned c = (lane <= firstp) ? val : 0u;
#pragma unroll
                    for (int d = 16; d; d >>= 1)
                        c += __shfl_xor_sync(0xffffffffu, c, d);
                    excl += c;
                    break;
                } else {
                    unsigned c = val;
#pragma unroll
                    for (int d = 16; d; d >>= 1)
                        c += __shfl_xor_sync(0xffffffffu, c, d);
                    excl += c;
                    base -= 32;
                }
            }
            if (lane == 0) {
                atomicExch(&g_scanstate[b],
                           (2ULL << 32) | (unsigned)(excl + total));
                sh_excl = (int)excl;
            }
        }
    }
    __syncthreads();
    int excl = sh_excl;

    if (i < N_TOTAL) {
        g_off[i + 1] = incl + excl;
        g_deg[i] = 0;                       // clean for next replay's hist
    }
    if (i == 0) g_off[0] = 0;

    // last-finishing block resets lookback state + ticket
    __threadfence();
    if (threadIdx.x == 0) {
        if (atomicAdd(&g_scan_ticket, 1) == gridDim.x - 1) {
            for (int k = 0; k < N_SCANBLK; k++) g_scanstate[k] = 0ULL;
            g_scan_ticket = 0;
        }
    }
}

// ---------------------------------------------------------------------------
// fill: p = g_off[r]++ (after fill, g_off[r] = start of row r+1)
// ---------------------------------------------------------------------------
__global__ void fill_kernel(const void* __restrict__ edge_index,
                            const float* __restrict__ edge_weight) {
    int is64 = block_idx_is64(edge_index);
    int e = blockIdx.x * blockDim.x + threadIdx.x;
    if (e >= N_EDGES) return;
    int r, c;
    if (is64) {
        const long long* ei = (const long long*)edge_index;
        r = (int)__ldg(&ei[e]);
        c = (int)__ldg(&ei[N_EDGES + e]);
    } else {
        const int* ei = (const int*)edge_index;
        r = __ldg(&ei[e]);
        c = __ldg(&ei[N_EDGES + e]);
    }
    int p = atomicAdd(&g_off[r], 1);
    g_cw[p] = make_int2(c, __float_as_int(__ldg(&edge_weight[e])));
}

// ---------------------------------------------------------------------------
// pull: 16 threads per node, lane j owns 4 features (one uint2 of half2s).
// Post-fill offsets: row n spans [ n? g_off[n-1]:0 , g_off[n] ).
// FINAL=0: write fp16 row to dst.
// FINAL=1: out = 0.25 * (x0_fp32 + h1 + h2 + a), fp32 output.
// ---------------------------------------------------------------------------
template <int FINAL>
__global__ void __launch_bounds__(256, 8)
pull_kernel(const uint2* __restrict__ src,
            uint2* __restrict__ dst,
            const float4* __restrict__ eu,   // x0 user (fp32)
            const float4* __restrict__ ei,   // x0 item (fp32)
            const uint2* __restrict__ h1,
            const uint2* __restrict__ h2,
            float4* __restrict__ out) {
    int gid = blockIdx.x * blockDim.x + threadIdx.x;
    int n = gid >> 4;
    int j = gid & 15;
    if (n >= N_TOTAL) return;

    int s = (n == 0) ? 0 : __ldg(&g_off[n - 1]);
    int t = __ldg(&g_off[n]);

    float ax = 0.f, ay = 0.f, az = 0.f, aw = 0.f;
    int e = s;

#define EDGE_STEP(K)                                                          \
    {                                                                         \
        int2 cw = __ldg(&g_cw[e + K]);                                        \
        float w = __int_as_float(cw.y);                                       \
        uint2 p = __ldg(&src[(long long)cw.x * 16 + j]);                      \
        float2 f01 = __half22float2(*(__half2*)&p.x);                         \
        float2 f23 = __half22float2(*(__half2*)&p.y);                         \
        ax += f01.x * w; ay += f01.y * w;                                     \
        az += f23.x * w; aw += f23.y * w;                                     \
    }

    for (; e + 4 <= t; e += 4) {
        EDGE_STEP(0) EDGE_STEP(1) EDGE_STEP(2) EDGE_STEP(3)
    }
    for (; e < t; e++) {
        EDGE_STEP(0)
    }
#undef EDGE_STEP

    long long oi = (long long)n * 16 + j;
    if (FINAL) {
        float4 x0 = (n < N_USERS)
                        ? __ldg(&eu[oi])
                        : __ldg(&ei[(long long)(n - N_USERS) * 16 + j]);
        uint2 p1 = __ldg(&h1[oi]);
        uint2 p2 = __ldg(&h2[oi]);
        float2 a01 = __half22float2(*(__half2*)&p1.x);
        float2 a23 = __half22float2(*(__half2*)&p1.y);
        float2 b01 = __half22float2(*(__half2*)&p2.x);
        float2 b23 = __half22float2(*(__half2*)&p2.y);
        out[oi] = make_float4((x0.x + a01.x + b01.x + ax) * 0.25f,
                              (x0.y + a01.y + b01.y + ay) * 0.25f,
                              (x0.z + a23.x + b23.x + az) * 0.25f,
                              (x0.w + a23.y + b23.y + aw) * 0.25f);
    } else {
        dst[oi] = pack_h4(make_float4(ax, ay, az, aw));
    }
}

// ---------------------------------------------------------------------------
// side stream + fork/join events, created once at module load
// ---------------------------------------------------------------------------
namespace {
struct HxSide {
    cudaStream_t s2 = nullptr;
    cudaEvent_t  evF = nullptr;
    cudaEvent_t  evJ = nullptr;
    HxSide() {
        if (cudaStreamCreateWithFlags(&s2, cudaStreamNonBlocking) != cudaSuccess) {
            s2 = nullptr;
            return;
        }
        if (cudaEventCreateWithFlags(&evF, cudaEventDisableTiming) != cudaSuccess)
            evF = nullptr;
        if (cudaEventCreateWithFlags(&evJ, cudaEventDisableTiming) != cudaSuccess)
            evJ = nullptr;
    }
};
HxSide g_side;
}

extern "C" void kernel_launch(void* const* d_in, const int* in_sizes, int n_in,
                              void* d_out, int out_size) {
    const void* edge_index   = d_in[0];
    const float* edge_weight = (const float*)d_in[1];
    const float4* user_emb   = (const float4*)d_in[2];
    const float4* item_emb   = (const float4*)d_in[3];
    float4* out              = (float4*)d_out;

    uint2 *h0, *h1, *h2;
    cudaGetSymbolAddress((void**)&h0, g_h0);
    cudaGetSymbolAddress((void**)&h1, g_h1);
    cudaGetSymbolAddress((void**)&h2, g_h2);

    const int TPB = 256;
    const int GRID_CONV = (N_F4 + TPB - 1) / TPB;
    const int GRID_EDGE = (N_EDGES + TPB - 1) / TPB;
    const int GRID_PULL = (N_TOTAL * 16 + TPB - 1) / TPB;

    const bool par = g_side.s2 && g_side.evF && g_side.evJ;

    if (par) {
        // fork at t=0: convert runs on s2 concurrently with the CSR build
        cudaEventRecord(g_side.evF, 0);
        cudaStreamWaitEvent(g_side.s2, g_side.evF, 0);
        convert_kernel<<<GRID_CONV, TPB, 0, g_side.s2>>>(user_emb, item_emb);
        cudaEventRecord(g_side.evJ, g_side.s2);
    } else {
        convert_kernel<<<GRID_CONV, TPB>>>(user_emb, item_emb);
    }

    // CSR build (main stream)
    hist_kernel<<<GRID_EDGE, TPB>>>(edge_index);
    scan_kernel<<<N_SCANBLK, SCAN_BLK>>>();
    fill_kernel<<<GRID_EDGE, TPB>>>(edge_index, edge_weight);

    if (par) cudaStreamWaitEvent(0, g_side.evJ, 0);   // pulls need h0

    // h1 = A h0 ; h2 = A h1 ; out = 0.25*(x0 + h1 + h2 + A h2)
    pull_kernel<0><<<GRID_PULL, TPB>>>(h0, h1, nullptr, nullptr,
                                       nullptr, nullptr, nullptr);
    pull_kernel<0><<<GRID_PULL, TPB>>>(h1, h2, nullptr, nullptr,
                                       nullptr, nullptr, nullptr);
    pull_kernel<1><<<GRID_PULL, TPB>>>(h2, nullptr, user_emb, item_emb,
                                       h1, h2, out);
}